// round 6
// baseline (speedup 1.0000x reference)
#include <cuda_runtime.h>
#include <cuda_bf16.h>
#include <cstdint>

// LocalitySensitiveHashing_29111288333011
//
// Mathematical collapse (holds for ALL inputs): the 'bqhk,bkhk->bhqk' einsum
// has no contracted index (repeated k = diagonal), so sim is an elementwise
// product of sign() values in {-1,0,+1}, scaled by 1/hash_bits (2048) and
// averaged over 8 heads: |sim| <= 1/2048 = 4.88e-4 < SIM_THRESHOLD = 0.3.
// (sim > 0.3) is identically False -> output == zeros([2,2048,2048], f32).
// Optimal kernel = pure 32 MiB zero-fill; no input is read.
//
// Measured wall: STG.128 x1, STG.128 x8, driver memset, and TMA bulk store
// all pin at ~4.3-4.5 TB/s (DRAM 0%) -> chip-level L2-write cap at bench
// clocks. __stcs (evict-first) gave the only kernel-time gain (7.81->7.46us).
// This round: 256-bit streaming stores (st.global.cs.v8.f32, sm_100+) —
// halves store-instruction count; expected ~flat (byte-wall-bound), closes
// the store-width experiment matrix.

#define ZB_THREADS 256
#define ZB_BLOCK_BYTES 32768   // 256 thr * 32 B * 4 iters

__global__ __launch_bounds__(ZB_THREADS)
void lsh_zero_v8_kernel(char* __restrict__ out) {
    // Exact-cover launch: no bounds checks. Each thread writes 4 x 32 B.
    unsigned long long addr = (unsigned long long)out
                            + (unsigned long long)blockIdx.x * ZB_BLOCK_BYTES
                            + (unsigned int)threadIdx.x * 32u;
    float z = 0.0f;
    #pragma unroll
    for (int j = 0; j < 4; j++) {
        asm volatile(
            "st.global.cs.v8.f32 [%0], {%1,%1,%1,%1,%1,%1,%1,%1};"
            :: "l"(addr + (unsigned long long)j * (ZB_THREADS * 32u)), "f"(z)
            : "memory");
    }
}

// Generic fallback/tail (not launched for this shape).
__global__ void lsh_zero_tail_kernel(float* __restrict__ out, long long n) {
    long long i = (long long)blockIdx.x * blockDim.x + threadIdx.x;
    if (i < n) out[i] = 0.0f;
}

extern "C" void kernel_launch(void* const* d_in, const int* in_sizes, int n_in,
                              void* d_out, int out_size) {
    (void)d_in; (void)in_sizes; (void)n_in;

    float* out = (float*)d_out;
    long long total_bytes = (long long)out_size * 4;          // 33,554,432
    long long blocks      = total_bytes / ZB_BLOCK_BYTES;     // 1024 (exact)
    long long covered     = blocks * ZB_BLOCK_BYTES;          // bytes

    if (blocks > 0) {
        lsh_zero_v8_kernel<<<(unsigned int)blocks, ZB_THREADS>>>((char*)out);
    }
    long long rem_floats = (total_bytes - covered) / 4;       // 0 for this shape
    if (rem_floats > 0) {
        long long tb = (rem_floats + 255) / 256;
        lsh_zero_tail_kernel<<<(unsigned int)tb, 256>>>(
            out + covered / 4, rem_floats);
    }
}